// round 14
// baseline (speedup 1.0000x reference)
#include <cuda_runtime.h>
#include <cuda_bf16.h>
#include <cstdint>

#define M_TOTAL 32768
#define K_DIM   256
#define NCODES  8192
#define MT      128
#define NSPLIT  4
#define STRIPE  2048
#define NT      128
#define CHUNKS  16            // 16 full-K tiles per stripe
#define THREADS 512
#define TAU     3.0f
#define QSCALE  25.0f
#define INV_S2  (1.0f/625.0f)

// SMEM layout (bytes)
#define A_STRIDE_B  272       // 256 int8 + 16 pad
#define B_STRIDE_B  272
#define SM_A        0         // 128*272 = 34816
#define SM_B        34816     // 4 stages * 34816 = 139264
#define B_STAGE_B   34816
#define SM_HESQ     174080    // 2048 floats = 8192
#define SMEM_TOTAL  182272
#define SM_MERGE    SM_B      // reuse B ring stages 0-1 after main loop (65536)

// device globals
__device__ float          g_hesq[NCODES];
__device__ float          g_embT[(size_t)NCODES * K_DIM];
__device__ int8_t         g_e8[(size_t)NCODES * K_DIM];    // [n][k]
__device__ int8_t         g_x8[(size_t)M_TOTAL * K_DIM];   // [m][k]
__device__ float          g_pv8[NSPLIT][M_TOTAL][8];
__device__ unsigned       g_pi8[NSPLIT][M_TOTAL][8];
__device__ float          g_pb[NSPLIT][M_TOTAL];
__device__ unsigned       g_idx[M_TOTAL];
__device__ unsigned       g_cand32[M_TOTAL][32];
__device__ int            g_nflag;
__device__ int            g_flag[M_TOTAL];
__device__ int            g_nflag2;
__device__ int            g_flag2[M_TOTAL];

// ---- helpers -------------------------------------------------------------
__device__ __forceinline__ uint32_t smem_u32(const void* p) {
    uint32_t a;
    asm("{ .reg .u64 t; cvta.to.shared.u64 t, %1; cvt.u32.u64 %0, t; }" : "=r"(a) : "l"(p));
    return a;
}
__device__ __forceinline__ void cpa16(uint32_t dst, const void* src) {
    asm volatile("cp.async.cg.shared.global [%0], [%1], 16;" :: "r"(dst), "l"(src));
}
#define CP_COMMIT() asm volatile("cp.async.commit_group;" ::: "memory")
#define CP_WAIT2()  asm volatile("cp.async.wait_group 2;" ::: "memory")

__device__ __forceinline__ void ldm4(uint32_t* r, uint32_t addr) {
    asm volatile("ldmatrix.sync.aligned.m8n8.x4.shared.b16 {%0,%1,%2,%3}, [%4];"
                 : "=r"(r[0]), "=r"(r[1]), "=r"(r[2]), "=r"(r[3]) : "r"(addr));
}
__device__ __forceinline__ void mma_s8(int* d, const uint32_t* a, uint32_t b0, uint32_t b1) {
    asm volatile("mma.sync.aligned.m16n8k32.row.col.s32.s8.s8.s32 "
                 "{%0,%1,%2,%3},{%4,%5,%6,%7},{%8,%9},{%0,%1,%2,%3};"
                 : "+r"(d[0]), "+r"(d[1]), "+r"(d[2]), "+r"(d[3])
                 : "r"(a[0]), "r"(a[1]), "r"(a[2]), "r"(a[3]), "r"(b0), "r"(b1));
}
__device__ __forceinline__ int q8(float v) {
    float s = fminf(fmaxf(v * QSCALE, -127.f), 127.f);
    return __float2int_rn(s);
}

// ---------------------------------------------------------------------------
// prep kernels
// ---------------------------------------------------------------------------
__global__ void prep_kernel(const float* __restrict__ embed) {
    int n = blockIdx.x * blockDim.x + threadIdx.x;
    if (n == 0) { g_nflag = 0; g_nflag2 = 0; }
    if (n < NCODES) {
        float s = 0.f;
        #pragma unroll 8
        for (int k = 0; k < K_DIM; k++) {
            float v = embed[(size_t)k * NCODES + n];
            s += v * v;
        }
        g_hesq[n] = 0.5f * s;
    }
}

__global__ void transpose_split_kernel(const float* __restrict__ embed) {
    __shared__ float tile[32][33];
    int bx = blockIdx.x, by = blockIdx.y;
    int tx = threadIdx.x, ty = threadIdx.y;
    tile[ty][tx] = embed[(size_t)(by * 32 + ty) * NCODES + bx * 32 + tx];
    __syncthreads();
    float v = tile[tx][ty];
    int n = bx * 32 + ty, k = by * 32 + tx;
    size_t o = (size_t)n * K_DIM + k;
    g_embT[o] = v;
    g_e8[o] = (int8_t)q8(v);
}

__global__ void xq_kernel(const float* __restrict__ x) {
    int i = blockIdx.x * blockDim.x + threadIdx.x;   // float4 index
    float4 v = reinterpret_cast<const float4*>(x)[i];
    unsigned w = ((unsigned)(q8(v.x) & 255))
               | ((unsigned)(q8(v.y) & 255) << 8)
               | ((unsigned)(q8(v.z) & 255) << 16)
               | ((unsigned)(q8(v.w) & 255) << 24);
    reinterpret_cast<unsigned*>(g_x8)[i] = w;
}

// ---------------------------------------------------------------------------
// fused int8 IMMA filter GEMM + per-stripe top-8
// ---------------------------------------------------------------------------
extern __shared__ char smc[];

__device__ __forceinline__ void issue_chunk(uint32_t smem, int c, int tid, int nstart) {
    const char* base = (const char*)g_e8 + (size_t)(nstart + c * NT) * K_DIM;
    uint32_t dst = smem + SM_B + (uint32_t)(c & 3) * B_STAGE_B;
    #pragma unroll
    for (int j = 0; j < 4; j++) {
        int i = tid + j * THREADS;          // 0..2047
        int n = i >> 4, ch = i & 15;
        cpa16(dst + n * B_STRIDE_B + ch * 16, base + (size_t)n * K_DIM + ch * 16);
    }
}

__global__ void __launch_bounds__(THREADS, 1)
score_kernel() {
    const int tid = threadIdx.x;
    const int lane = tid & 31;
    const int warp = tid >> 5;
    const int mwarp = warp >> 2;            // 0..3 (32 rows each)
    const int nwarp = warp & 3;             // 0..3 (32 cols each)
    const int r0 = blockIdx.x * MT;
    const int nstart = blockIdx.y * STRIPE;
    const uint32_t smem = smem_u32(smc);

    // ---- prologue: A (int8) + hesq stripe, then 2 B chunks ----
    {
        const char* xr = (const char*)g_x8 + (size_t)r0 * K_DIM;
        #pragma unroll
        for (int j = 0; j < 4; j++) {
            int i = tid + j * THREADS;      // 0..2047
            int row = i >> 4, ch = i & 15;
            cpa16(smem + SM_A + row * A_STRIDE_B + ch * 16, xr + (size_t)row * K_DIM + ch * 16);
        }
        for (int i = tid; i < 512; i += THREADS)
            cpa16(smem + SM_HESQ + i * 16, g_hesq + nstart + i * 4);
        CP_COMMIT();
        issue_chunk(smem, 0, tid, nstart); CP_COMMIT();
        issue_chunk(smem, 1, tid, nstart); CP_COMMIT();
    }

    int acc[2][4][4];                       // [m16 half][n8 block][frag]
    float tv[4][4];
    unsigned ti[4][4];
    #pragma unroll
    for (int r = 0; r < 4; r++)
        #pragma unroll
        for (int j = 0; j < 4; j++) { tv[r][j] = 3.4e38f; ti[r][j] = 0; }

    const uint32_t a_lane = (uint32_t)((lane & 15) * A_STRIDE_B + (lane >> 4) * 16);
    const uint32_t b_lane = (uint32_t)((lane & 15) * B_STRIDE_B + (lane >> 4) * 16);
    const uint32_t aBase = smem + SM_A + mwarp * 32 * A_STRIDE_B + a_lane;
    const float* hesq_s = (const float*)(smc + SM_HESQ);

    for (int c = 0; c < CHUNKS; c++) {
        if (c + 2 < CHUNKS) issue_chunk(smem, c + 2, tid, nstart);
        CP_COMMIT();
        CP_WAIT2();
        __syncthreads();

        const uint32_t Bb = smem + SM_B + (uint32_t)(c & 3) * B_STAGE_B
                          + (uint32_t)(nwarp * 32) * B_STRIDE_B + b_lane;

        #pragma unroll
        for (int ms = 0; ms < 2; ms++)
            #pragma unroll
            for (int ns = 0; ns < 4; ns++)
                #pragma unroll
                for (int j = 0; j < 4; j++) acc[ms][ns][j] = 0;

        // 8 k32 steps: fresh fragments, 8 independent IMMAs each
        #pragma unroll
        for (int ks = 0; ks < 8; ks++) {
            const uint32_t ko = (uint32_t)ks * 32;
            uint32_t a0[4], a1[4], bA[4], bB[4];
            ldm4(a0, aBase + ko);
            ldm4(a1, aBase + ko + 16 * A_STRIDE_B);
            ldm4(bA, Bb + ko);
            ldm4(bB, Bb + ko + 16 * B_STRIDE_B);
            mma_s8(acc[0][0], a0, bA[0], bA[2]);
            mma_s8(acc[1][0], a1, bA[0], bA[2]);
            mma_s8(acc[0][1], a0, bA[1], bA[3]);
            mma_s8(acc[1][1], a1, bA[1], bA[3]);
            mma_s8(acc[0][2], a0, bB[0], bB[2]);
            mma_s8(acc[1][2], a1, bB[0], bB[2]);
            mma_s8(acc[0][3], a0, bB[1], bB[3]);
            mma_s8(acc[1][3], a1, bB[1], bB[3]);
        }

        // tile done: score + top-4 per thread slot
        {
            const int colbase = c * NT + nwarp * 32 + (lane & 3) * 2;
            #pragma unroll
            for (int ms = 0; ms < 2; ms++)
                #pragma unroll
                for (int ns = 0; ns < 4; ns++)
                    #pragma unroll
                    for (int i = 0; i < 4; i++) {
                        int col = colbase + ns * 8 + (i & 1);
                        float s = hesq_s[col] - (float)acc[ms][ns][i] * INV_S2;
                        const int rid = ms * 2 + (i >> 1);
                        if (s < tv[rid][3]) {
                            unsigned n = (unsigned)(nstart + col);
                            if (s < tv[rid][0]) {
                                tv[rid][3]=tv[rid][2]; ti[rid][3]=ti[rid][2];
                                tv[rid][2]=tv[rid][1]; ti[rid][2]=ti[rid][1];
                                tv[rid][1]=tv[rid][0]; ti[rid][1]=ti[rid][0];
                                tv[rid][0]=s; ti[rid][0]=n;
                            } else if (s < tv[rid][1]) {
                                tv[rid][3]=tv[rid][2]; ti[rid][3]=ti[rid][2];
                                tv[rid][2]=tv[rid][1]; ti[rid][2]=ti[rid][1];
                                tv[rid][1]=s; ti[rid][1]=n;
                            } else if (s < tv[rid][2]) {
                                tv[rid][3]=tv[rid][2]; ti[rid][3]=ti[rid][2];
                                tv[rid][2]=s; ti[rid][2]=n;
                            } else { tv[rid][3]=s; ti[rid][3]=n; }
                        }
                    }
        }
    }

    // ---- per-CTA merge: 16 slots x top-4 per row -> stripe top-8 + bound --
    char* scr = smc + SM_MERGE;
    const int slot = nwarp * 4 + (lane & 3);
    #pragma unroll
    for (int rid = 0; rid < 4; rid++) {
        int row = mwarp * 32 + (rid >> 1) * 16 + (rid & 1) * 8 + (lane >> 2);
        char* p = scr + (row * 16 + slot) * 32;
        *reinterpret_cast<float4*>(p)      = make_float4(tv[rid][0], tv[rid][1], tv[rid][2], tv[rid][3]);
        *reinterpret_cast<uint4*>(p + 16)  = make_uint4(ti[rid][0], ti[rid][1], ti[rid][2], ti[rid][3]);
    }
    __syncthreads();

    if (tid < MT) {
        float v[8];
        unsigned id[8];
        for (int j = 0; j < 8; j++) { v[j] = 3.4e38f; id[j] = 0; }
        float Lb = 3.4e38f;
        const char* p = scr + tid * 16 * 32;
        for (int s = 0; s < 16; s++) {
            float4 pv = *reinterpret_cast<const float4*>(p + s * 32);
            uint4  pi = *reinterpret_cast<const uint4*>(p + s * 32 + 16);
            Lb = fminf(Lb, pv.w);            // unlisted-in-slot >= slot 4th best
            float cv[4] = {pv.x, pv.y, pv.z, pv.w};
            unsigned ci[4] = {pi.x, pi.y, pi.z, pi.w};
            for (int j = 0; j < 4; j++) {
                float s1 = cv[j]; unsigned n1 = ci[j];
                if (s1 < v[7] || (s1 == v[7] && n1 < id[7])) {
                    int q = 7;
                    while (q > 0 && (s1 < v[q-1] || (s1 == v[q-1] && n1 < id[q-1]))) {
                        v[q] = v[q-1]; id[q] = id[q-1]; q--;
                    }
                    v[q] = s1; id[q] = n1;
                }
            }
        }
        int row = r0 + tid;
        for (int j = 0; j < 8; j++) {
            g_pv8[blockIdx.y][row][j] = v[j];
            g_pi8[blockIdx.y][row][j] = id[j];
        }
        // stripe bound: unlisted codes >= min(merged 8th, min slot 4th)
        g_pb[blockIdx.y][row] = fminf(v[7], Lb);
    }
}

// ---------------------------------------------------------------------------
// merge stripes + certify; push uncertain rows to queues
// ---------------------------------------------------------------------------
__global__ void merge_kernel() {
    int r = blockIdx.x * blockDim.x + threadIdx.x;
    float v0 = 3.4e38f, v1 = 3.4e38f;
    unsigned i0 = 0, i1 = 0;
    float L = 3.4e38f;
    unsigned cand[32];
    #pragma unroll
    for (int s = 0; s < NSPLIT; s++) {
        L = fminf(L, g_pb[s][r]);
        #pragma unroll
        for (int j = 0; j < 8; j++) {
            float sv = g_pv8[s][r][j];
            unsigned n = g_pi8[s][r][j];
            cand[s * 8 + j] = n;
            if (sv < v0 || (sv == v0 && n < i0)) { v1 = v0; i1 = i0; v0 = sv; i0 = n; }
            else if (sv < v1 || (sv == v1 && n < i1)) { v1 = sv; i1 = n; }
        }
    }
    g_idx[r] = i0;                     // provisional winner
    if (v1 - v0 >= TAU) return;        // certified: margin >> quant error

    #pragma unroll
    for (int j = 0; j < 32; j++) g_cand32[r][j] = cand[j];
    int p = atomicAdd(&g_nflag, 1);
    g_flag[p] = r;
    if (L - v0 < TAU) {                // candidate set not certified complete
        int q = atomicAdd(&g_nflag2, 1);
        g_flag2[q] = r;
    }
}

// ---------------------------------------------------------------------------
// warp-per-row exact fp32 rescore of the 32 candidates
// ---------------------------------------------------------------------------
__global__ void rescore_kernel(const float* __restrict__ x) {
    int nf = g_nflag;
    int gw = (blockIdx.x * blockDim.x + threadIdx.x) >> 5;
    int lane = threadIdx.x & 31;
    int nw = (gridDim.x * blockDim.x) >> 5;
    for (int f = gw; f < nf; f += nw) {
        int r = g_flag[f];
        unsigned n = g_cand32[r][lane];
        const float4* xv = reinterpret_cast<const float4*>(x + (size_t)r * K_DIM);
        const float4* ev = reinterpret_cast<const float4*>(g_embT + (size_t)n * K_DIM);
        float dot = 0.f;
        #pragma unroll 8
        for (int k = 0; k < K_DIM / 4; k++) {
            float4 a = xv[k], b = ev[k];
            dot += a.x * b.x + a.y * b.y + a.z * b.z + a.w * b.w;
        }
        float best = g_hesq[n] - dot;
        unsigned bi = n;
        #pragma unroll
        for (int off = 1; off < 32; off <<= 1) {
            float ov = __shfl_xor_sync(0xffffffffu, best, off);
            unsigned oi = __shfl_xor_sync(0xffffffffu, bi, off);
            if (ov < best || (ov == best && oi < bi)) { best = ov; bi = oi; }
        }
        if (lane == 0) g_idx[r] = bi;
    }
}

// ---------------------------------------------------------------------------
// full exact argmin for rare uncertified rows
// ---------------------------------------------------------------------------
__global__ void fixup_full_kernel(const float* __restrict__ x) {
    __shared__ float xs[K_DIM];
    __shared__ float wv[8];
    __shared__ unsigned wi[8];
    int nf = g_nflag2;
    for (int f = blockIdx.x; f < nf; f += gridDim.x) {
        int r = g_flag2[f];
        for (int k = threadIdx.x; k < K_DIM; k += blockDim.x) xs[k] = x[(size_t)r * K_DIM + k];
        __syncthreads();
        float best = 3.4e38f; unsigned bi = 0xFFFFFFFFu;
        for (int n = threadIdx.x; n < NCODES; n += blockDim.x) {
            const float4* er = reinterpret_cast<const float4*>(g_embT + (size_t)n * K_DIM);
            float dot = 0.f;
            #pragma unroll 8
            for (int k = 0; k < K_DIM / 4; k++) {
                float4 b = er[k];
                dot += xs[4*k] * b.x + xs[4*k+1] * b.y + xs[4*k+2] * b.z + xs[4*k+3] * b.w;
            }
            float s = g_hesq[n] - dot;
            if (s < best || (s == best && n < bi)) { best = s; bi = n; }
        }
        #pragma unroll
        for (int off = 16; off > 0; off >>= 1) {
            float ov = __shfl_down_sync(0xffffffffu, best, off);
            unsigned oi = __shfl_down_sync(0xffffffffu, bi, off);
            if (ov < best || (ov == best && oi < bi)) { best = ov; bi = oi; }
        }
        if ((threadIdx.x & 31) == 0) { wv[threadIdx.x >> 5] = best; wi[threadIdx.x >> 5] = bi; }
        __syncthreads();
        if (threadIdx.x == 0) {
            for (int w = 1; w < 8; w++)
                if (wv[w] < best || (wv[w] == best && wi[w] < bi)) { best = wv[w]; bi = wi[w]; }
            g_idx[r] = bi;
        }
        __syncthreads();
    }
}

// ---------------------------------------------------------------------------
__global__ void gather_kernel(float* __restrict__ out) {
    int r = blockIdx.x * 4 + (threadIdx.x >> 6);
    int c = threadIdx.x & 63;
    unsigned idx = g_idx[r] & (NCODES - 1);
    const float4* src = reinterpret_cast<const float4*>(g_embT + (size_t)idx * K_DIM);
    reinterpret_cast<float4*>(out + (size_t)r * K_DIM)[c] = src[c];
}

// ---------------------------------------------------------------------------
extern "C" void kernel_launch(void* const* d_in, const int* in_sizes, int n_in,
                              void* d_out, int out_size) {
    const float* x = (const float*)d_in[0];      // [32768, 256]
    const float* embed = (const float*)d_in[1];  // [256, 8192]
    float* out = (float*)d_out;

    cudaFuncSetAttribute(score_kernel, cudaFuncAttributeMaxDynamicSharedMemorySize,
                         SMEM_TOTAL);

    prep_kernel<<<NCODES / 256, 256>>>(embed);
    transpose_split_kernel<<<dim3(NCODES / 32, K_DIM / 32), dim3(32, 32)>>>(embed);
    xq_kernel<<<(M_TOTAL * K_DIM / 4) / 256, 256>>>(x);
    score_kernel<<<dim3(M_TOTAL / MT, NSPLIT), THREADS, SMEM_TOTAL>>>();
    merge_kernel<<<M_TOTAL / 256, 256>>>();
    rescore_kernel<<<256, 256>>>(x);
    fixup_full_kernel<<<256, 256>>>(x);
    gather_kernel<<<M_TOTAL / 4, 256>>>(out);
}

// round 15
// speedup vs baseline: 1.7351x; 1.7351x over previous
#include <cuda_runtime.h>
#include <cuda_fp16.h>
#include <cstdint>

#define M_TOTAL 32768
#define K_DIM   256
#define NCODES  8192
#define MT      128
#define NSPLIT  4
#define STRIPE  2048
#define NT      128
#define CHUNKS  32            // 16 tiles * 2 half-k chunks
#define THREADS 512
#define TAU     0.6f

// SMEM layout (bytes)
#define A_STRIDE_B  528       // 256 f16 + 8 pad
#define B_STRIDE_B  272       // 128 f16 + 8 pad
#define SM_A        0         // 128*528 = 67584
#define SM_B        67584     // 4 stages * 34816 = 139264
#define B_STAGE_B   34816
#define SM_HESQ     206848    // 2048 floats = 8192
#define SMEM_TOTAL  215040
#define SM_MERGE    SM_B      // reuse B ring after main loop (128*16*32 = 65536)

// device globals
__device__ float          g_hesq[NCODES];
__device__ float          g_embT[(size_t)NCODES * K_DIM];
__device__ __half         g_ehf[(size_t)NCODES * K_DIM];
__device__ __half         g_xhf[(size_t)M_TOTAL * K_DIM];
__device__ float4         g_pvals[NSPLIT][M_TOTAL];
__device__ uint4          g_pidx[NSPLIT][M_TOTAL];
__device__ unsigned       g_idx[M_TOTAL];
__device__ unsigned       g_cand16[M_TOTAL][16];
__device__ int            g_nflag;           // rescore queue
__device__ int            g_flag[M_TOTAL];
__device__ int            g_nflag2;          // full-scan queue
__device__ int            g_flag2[M_TOTAL];

// ---- helpers -------------------------------------------------------------
__device__ __forceinline__ uint32_t smem_u32(const void* p) {
    uint32_t a;
    asm("{ .reg .u64 t; cvta.to.shared.u64 t, %1; cvt.u32.u64 %0, t; }" : "=r"(a) : "l"(p));
    return a;
}
__device__ __forceinline__ void cpa16(uint32_t dst, const void* src) {
    asm volatile("cp.async.cg.shared.global [%0], [%1], 16;" :: "r"(dst), "l"(src));
}
#define CP_COMMIT() asm volatile("cp.async.commit_group;" ::: "memory")
#define CP_WAIT2()  asm volatile("cp.async.wait_group 2;" ::: "memory")

__device__ __forceinline__ void ldm4(uint32_t* r, uint32_t addr) {
    asm volatile("ldmatrix.sync.aligned.m8n8.x4.shared.b16 {%0,%1,%2,%3}, [%4];"
                 : "=r"(r[0]), "=r"(r[1]), "=r"(r[2]), "=r"(r[3]) : "r"(addr));
}
// f16 x f16 -> f16 accumulate (double-rate legacy HMMA)
__device__ __forceinline__ void mma_f16(uint32_t* d, const uint32_t* a, uint32_t b0, uint32_t b1) {
    asm volatile("mma.sync.aligned.m16n8k16.row.col.f16.f16.f16.f16 "
                 "{%0,%1},{%2,%3,%4,%5},{%6,%7},{%0,%1};"
                 : "+r"(d[0]), "+r"(d[1])
                 : "r"(a[0]), "r"(a[1]), "r"(a[2]), "r"(a[3]), "r"(b0), "r"(b1));
}

// ---------------------------------------------------------------------------
// prep kernels
// ---------------------------------------------------------------------------
__global__ void prep_kernel(const float* __restrict__ embed) {
    int n = blockIdx.x * blockDim.x + threadIdx.x;
    if (n == 0) { g_nflag = 0; g_nflag2 = 0; }
    if (n < NCODES) {
        float s = 0.f;
        #pragma unroll 8
        for (int k = 0; k < K_DIM; k++) {
            float v = embed[(size_t)k * NCODES + n];
            s += v * v;
        }
        g_hesq[n] = 0.5f * s;
    }
}

__global__ void transpose_split_kernel(const float* __restrict__ embed) {
    __shared__ float tile[32][33];
    int bx = blockIdx.x, by = blockIdx.y;
    int tx = threadIdx.x, ty = threadIdx.y;
    tile[ty][tx] = embed[(size_t)(by * 32 + ty) * NCODES + bx * 32 + tx];
    __syncthreads();
    float v = tile[tx][ty];
    int n = bx * 32 + ty, k = by * 32 + tx;
    size_t o = (size_t)n * K_DIM + k;
    g_embT[o] = v;
    g_ehf[o] = __float2half_rn(v);
}

__global__ void xq_kernel(const float* __restrict__ x) {
    int i = blockIdx.x * blockDim.x + threadIdx.x;   // float4 index
    float4 v = reinterpret_cast<const float4*>(x)[i];
    __half2 h0 = __floats2half2_rn(v.x, v.y);
    __half2 h1 = __floats2half2_rn(v.z, v.w);
    reinterpret_cast<uint2*>(g_xhf)[i] =
        make_uint2(*reinterpret_cast<unsigned*>(&h0), *reinterpret_cast<unsigned*>(&h1));
}

// ---------------------------------------------------------------------------
// fused f16 HMMA filter GEMM + per-stripe top-4
// ---------------------------------------------------------------------------
extern __shared__ char smc[];

__device__ __forceinline__ void issue_chunk(uint32_t smem, int c, int tid, int nstart) {
    int t = c >> 1, h = c & 1;
    const char* base = (const char*)g_ehf
                     + (size_t)(nstart + t * NT) * 512 + h * 256;
    uint32_t dst = smem + SM_B + (uint32_t)(c & 3) * B_STAGE_B;
    #pragma unroll
    for (int j = 0; j < 4; j++) {
        int i = tid + j * THREADS;          // 0..2047
        int n = i >> 4, ch = i & 15;
        cpa16(dst + n * B_STRIDE_B + ch * 16, base + (size_t)n * 512 + ch * 16);
    }
}

__global__ void __launch_bounds__(THREADS, 1)
score_kernel() {
    const int tid = threadIdx.x;
    const int lane = tid & 31;
    const int warp = tid >> 5;
    const int mwarp = warp >> 2;            // 0..3 (32 rows each)
    const int nwarp = warp & 3;             // 0..3 (32 cols each)
    const int r0 = blockIdx.x * MT;
    const int nstart = blockIdx.y * STRIPE;
    const uint32_t smem = smem_u32(smc);

    // ---- prologue: A + hesq stripe, then 2 B chunks ----
    {
        const char* xh = (const char*)g_xhf + (size_t)r0 * 512;
        #pragma unroll
        for (int j = 0; j < 8; j++) {
            int i = tid + j * THREADS;      // 0..4095
            int row = i >> 5, ch = i & 31;
            cpa16(smem + SM_A + row * A_STRIDE_B + ch * 16, xh + (size_t)row * 512 + ch * 16);
        }
        for (int i = tid; i < 512; i += THREADS)
            cpa16(smem + SM_HESQ + i * 16, g_hesq + nstart + i * 4);
        CP_COMMIT();
        issue_chunk(smem, 0, tid, nstart); CP_COMMIT();
        issue_chunk(smem, 1, tid, nstart); CP_COMMIT();
    }

    uint32_t acc[2][4][2];                  // [m16 half][n8 block][f16x2 frag]
    float tv[4][4];
    unsigned ti[4][4];
    #pragma unroll
    for (int r = 0; r < 4; r++)
        #pragma unroll
        for (int j = 0; j < 4; j++) { tv[r][j] = 3.4e38f; ti[r][j] = 0; }

    const uint32_t a_lane = (uint32_t)((lane & 15) * A_STRIDE_B + (lane >> 4) * 16);
    const uint32_t b_lane = (uint32_t)((lane & 15) * B_STRIDE_B + (lane >> 4) * 16);
    const uint32_t aBase = smem + SM_A + mwarp * 32 * A_STRIDE_B + a_lane;
    const float* hesq_s = (const float*)(smc + SM_HESQ);

    for (int c = 0; c < CHUNKS; c++) {
        if (c + 2 < CHUNKS) issue_chunk(smem, c + 2, tid, nstart);
        CP_COMMIT();
        CP_WAIT2();
        __syncthreads();

        const int h = c & 1;
        const uint32_t aCh = aBase + (uint32_t)h * 256;   // k offset of this chunk
        const uint32_t Bb = smem + SM_B + (uint32_t)(c & 3) * B_STAGE_B
                          + (uint32_t)(nwarp * 32) * B_STRIDE_B + b_lane;

        if (h == 0) {
            #pragma unroll
            for (int ms = 0; ms < 2; ms++)
                #pragma unroll
                for (int ns = 0; ns < 4; ns++) {
                    acc[ms][ns][0] = 0u; acc[ms][ns][1] = 0u;
                }
        }

        // software-pipelined fragment double buffer over 8 k16 steps
        uint32_t bf[2][2][4], af[2][2][4];
        ldm4(bf[0][0], Bb);
        ldm4(bf[0][1], Bb + 16 * B_STRIDE_B);
        ldm4(af[0][0], aCh);
        ldm4(af[0][1], aCh + 16 * A_STRIDE_B);

        #pragma unroll
        for (int ks = 0; ks < 8; ks++) {
            const int cur = ks & 1, nxt = cur ^ 1;
            if (ks < 7) {
                const uint32_t ko = (ks + 1) * 32;
                ldm4(bf[nxt][0], Bb + ko);
                ldm4(bf[nxt][1], Bb + ko + 16 * B_STRIDE_B);
                ldm4(af[nxt][0], aCh + ko);
                ldm4(af[nxt][1], aCh + ko + 16 * A_STRIDE_B);
            }
            #pragma unroll
            for (int ns = 0; ns < 4; ns++) {
                uint32_t b0 = bf[cur][ns >> 1][ns & 1];
                uint32_t b1 = bf[cur][ns >> 1][(ns & 1) + 2];
                mma_f16(acc[0][ns], af[cur][0], b0, b1);
                mma_f16(acc[1][ns], af[cur][1], b0, b1);
            }
        }

        if (h == 1) {                        // tile done: score + top-4
            const int t = c >> 1;
            const int colbase = t * NT + nwarp * 32 + (lane & 3) * 2;
            #pragma unroll
            for (int ms = 0; ms < 2; ms++)
                #pragma unroll
                for (int ns = 0; ns < 4; ns++)
                    #pragma unroll
                    for (int reg = 0; reg < 2; reg++) {
                        // d0 = cols {colbase, colbase+1} @ row; d1 = @ row+8
                        float2 dv = __half22float2(
                            *reinterpret_cast<__half2*>(&acc[ms][ns][reg]));
                        const int rid = ms * 2 + reg;
                        #pragma unroll
                        for (int i = 0; i < 2; i++) {
                            int col = colbase + ns * 8 + i;
                            float s = hesq_s[col] - (i ? dv.y : dv.x);
                            if (s < tv[rid][3]) {
                                unsigned n = (unsigned)(nstart + col);
                                if (s < tv[rid][0]) {
                                    tv[rid][3]=tv[rid][2]; ti[rid][3]=ti[rid][2];
                                    tv[rid][2]=tv[rid][1]; ti[rid][2]=ti[rid][1];
                                    tv[rid][1]=tv[rid][0]; ti[rid][1]=ti[rid][0];
                                    tv[rid][0]=s; ti[rid][0]=n;
                                } else if (s < tv[rid][1]) {
                                    tv[rid][3]=tv[rid][2]; ti[rid][3]=ti[rid][2];
                                    tv[rid][2]=tv[rid][1]; ti[rid][2]=ti[rid][1];
                                    tv[rid][1]=s; ti[rid][1]=n;
                                } else if (s < tv[rid][2]) {
                                    tv[rid][3]=tv[rid][2]; ti[rid][3]=ti[rid][2];
                                    tv[rid][2]=s; ti[rid][2]=n;
                                } else { tv[rid][3]=s; ti[rid][3]=n; }
                            }
                        }
                    }
        }
    }

    // ---- per-CTA merge: 16 partial top-4 lists per row -> stripe top-4 ----
    char* scr = smc + SM_MERGE;
    const int slot = nwarp * 4 + (lane & 3);
    #pragma unroll
    for (int rid = 0; rid < 4; rid++) {
        int row = mwarp * 32 + (rid >> 1) * 16 + (rid & 1) * 8 + (lane >> 2);
        char* p = scr + (row * 16 + slot) * 32;
        *reinterpret_cast<float4*>(p)      = make_float4(tv[rid][0], tv[rid][1], tv[rid][2], tv[rid][3]);
        *reinterpret_cast<uint4*>(p + 16)  = make_uint4(ti[rid][0], ti[rid][1], ti[rid][2], ti[rid][3]);
    }
    __syncthreads();

    if (tid < MT) {
        float v[4] = {3.4e38f, 3.4e38f, 3.4e38f, 3.4e38f};
        unsigned id[4] = {0, 0, 0, 0};
        const char* p = scr + tid * 16 * 32;
        for (int s = 0; s < 16; s++) {
            float4 pv = *reinterpret_cast<const float4*>(p + s * 32);
            uint4  pi = *reinterpret_cast<const uint4*>(p + s * 32 + 16);
            float cv[4] = {pv.x, pv.y, pv.z, pv.w};
            unsigned ci[4] = {pi.x, pi.y, pi.z, pi.w};
            #pragma unroll
            for (int j = 0; j < 4; j++) {
                float s1 = cv[j]; unsigned n1 = ci[j];
                if (s1 < v[3] || (s1 == v[3] && n1 < id[3])) {
                    if (s1 < v[0] || (s1 == v[0] && n1 < id[0])) {
                        v[3]=v[2];id[3]=id[2]; v[2]=v[1];id[2]=id[1]; v[1]=v[0];id[1]=id[0]; v[0]=s1;id[0]=n1;
                    } else if (s1 < v[1] || (s1 == v[1] && n1 < id[1])) {
                        v[3]=v[2];id[3]=id[2]; v[2]=v[1];id[2]=id[1]; v[1]=s1;id[1]=n1;
                    } else if (s1 < v[2] || (s1 == v[2] && n1 < id[2])) {
                        v[3]=v[2];id[3]=id[2]; v[2]=s1;id[2]=n1;
                    } else { v[3]=s1; id[3]=n1; }
                }
            }
        }
        // v[3] is a valid lower bound for every code in this stripe not listed
        g_pvals[blockIdx.y][r0 + tid] = make_float4(v[0], v[1], v[2], v[3]);
        g_pidx[blockIdx.y][r0 + tid]  = make_uint4(id[0], id[1], id[2], id[3]);
    }
}

// ---------------------------------------------------------------------------
// merge stripes + certify; push uncertain rows to queues (no rescore here)
// ---------------------------------------------------------------------------
__global__ void merge_kernel() {
    int r = blockIdx.x * blockDim.x + threadIdx.x;
    float v[4] = {3.4e38f, 3.4e38f, 3.4e38f, 3.4e38f};
    unsigned id[4] = {0, 0, 0, 0};
    float L = 3.4e38f;
    unsigned alli[16];
    #pragma unroll
    for (int s = 0; s < NSPLIT; s++) {
        float4 pv = g_pvals[s][r];
        uint4  pi = g_pidx[s][r];
        if (pv.w < L) L = pv.w;
        float cv[4] = {pv.x, pv.y, pv.z, pv.w};
        unsigned ci[4] = {pi.x, pi.y, pi.z, pi.w};
        #pragma unroll
        for (int j = 0; j < 4; j++) {
            alli[s * 4 + j] = ci[j];
            float s1 = cv[j]; unsigned n1 = ci[j];
            if (s1 < v[3] || (s1 == v[3] && n1 < id[3])) {
                if (s1 < v[0] || (s1 == v[0] && n1 < id[0])) {
                    v[3]=v[2];id[3]=id[2]; v[2]=v[1];id[2]=id[1]; v[1]=v[0];id[1]=id[0]; v[0]=s1;id[0]=n1;
                } else if (s1 < v[1] || (s1 == v[1] && n1 < id[1])) {
                    v[3]=v[2];id[3]=id[2]; v[2]=v[1];id[2]=id[1]; v[1]=s1;id[1]=n1;
                } else if (s1 < v[2] || (s1 == v[2] && n1 < id[2])) {
                    v[3]=v[2];id[3]=id[2]; v[2]=s1;id[2]=n1;
                } else { v[3]=s1; id[3]=n1; }
            }
        }
    }
    g_idx[r] = id[0];                  // provisional winner
    if (v[1] - v[0] >= TAU) return;    // certified: margin >> approx error

    #pragma unroll
    for (int j = 0; j < 16; j++) g_cand16[r][j] = alli[j];
    int p = atomicAdd(&g_nflag, 1);
    g_flag[p] = r;
    if (L - v[0] < TAU) {              // candidate set not certified complete
        int q = atomicAdd(&g_nflag2, 1);
        g_flag2[q] = r;
    }
}

// ---------------------------------------------------------------------------
// warp-per-row exact fp32 rescore of the 16 candidates
// ---------------------------------------------------------------------------
__global__ void rescore_kernel(const float* __restrict__ x) {
    int nf = g_nflag;
    int gw = (blockIdx.x * blockDim.x + threadIdx.x) >> 5;
    int lane = threadIdx.x & 31;
    int nw = (gridDim.x * blockDim.x) >> 5;
    for (int f = gw; f < nf; f += nw) {
        int r = g_flag[f];
        unsigned n = g_cand16[r][lane >> 1];
        int half = lane & 1;
        const float4* xv = reinterpret_cast<const float4*>(x + (size_t)r * K_DIM) + half * 32;
        const float4* ev = reinterpret_cast<const float4*>(g_embT + (size_t)n * K_DIM) + half * 32;
        float dot = 0.f;
        #pragma unroll 8
        for (int k = 0; k < 32; k++) {
            float4 a = xv[k], b = ev[k];
            dot += a.x * b.x + a.y * b.y + a.z * b.z + a.w * b.w;
        }
        dot += __shfl_xor_sync(0xffffffffu, dot, 1);
        float best = g_hesq[n] - dot;
        unsigned bi = n;
        #pragma unroll
        for (int off = 2; off < 32; off <<= 1) {
            float ov = __shfl_xor_sync(0xffffffffu, best, off);
            unsigned oi = __shfl_xor_sync(0xffffffffu, bi, off);
            if (ov < best || (ov == best && oi < bi)) { best = ov; bi = oi; }
        }
        if (lane == 0) g_idx[r] = bi;
    }
}

// ---------------------------------------------------------------------------
// full exact argmin for rare uncertified rows
// ---------------------------------------------------------------------------
__global__ void fixup_full_kernel(const float* __restrict__ x) {
    __shared__ float xs[K_DIM];
    __shared__ float wv[8];
    __shared__ unsigned wi[8];
    int nf = g_nflag2;
    for (int f = blockIdx.x; f < nf; f += gridDim.x) {
        int r = g_flag2[f];
        for (int k = threadIdx.x; k < K_DIM; k += blockDim.x) xs[k] = x[(size_t)r * K_DIM + k];
        __syncthreads();
        float best = 3.4e38f; unsigned bi = 0xFFFFFFFFu;
        for (int n = threadIdx.x; n < NCODES; n += blockDim.x) {
            const float4* er = reinterpret_cast<const float4*>(g_embT + (size_t)n * K_DIM);
            float dot = 0.f;
            #pragma unroll 8
            for (int k = 0; k < K_DIM / 4; k++) {
                float4 b = er[k];
                dot += xs[4*k] * b.x + xs[4*k+1] * b.y + xs[4*k+2] * b.z + xs[4*k+3] * b.w;
            }
            float s = g_hesq[n] - dot;
            if (s < best || (s == best && n < bi)) { best = s; bi = n; }
        }
        #pragma unroll
        for (int off = 16; off > 0; off >>= 1) {
            float ov = __shfl_down_sync(0xffffffffu, best, off);
            unsigned oi = __shfl_down_sync(0xffffffffu, bi, off);
            if (ov < best || (ov == best && oi < bi)) { best = ov; bi = oi; }
        }
        if ((threadIdx.x & 31) == 0) { wv[threadIdx.x >> 5] = best; wi[threadIdx.x >> 5] = bi; }
        __syncthreads();
        if (threadIdx.x == 0) {
            for (int w = 1; w < 8; w++)
                if (wv[w] < best || (wv[w] == best && wi[w] < bi)) { best = wv[w]; bi = wi[w]; }
            g_idx[r] = bi;
        }
        __syncthreads();
    }
}

// ---------------------------------------------------------------------------
__global__ void gather_kernel(float* __restrict__ out) {
    int r = blockIdx.x * 4 + (threadIdx.x >> 6);
    int c = threadIdx.x & 63;
    unsigned idx = g_idx[r] & (NCODES - 1);
    const float4* src = reinterpret_cast<const float4*>(g_embT + (size_t)idx * K_DIM);
    reinterpret_cast<float4*>(out + (size_t)r * K_DIM)[c] = src[c];
}

// ---------------------------------------------------------------------------
extern "C" void kernel_launch(void* const* d_in, const int* in_sizes, int n_in,
                              void* d_out, int out_size) {
    const float* x = (const float*)d_in[0];      // [32768, 256]
    const float* embed = (const float*)d_in[1];  // [256, 8192]
    float* out = (float*)d_out;

    cudaFuncSetAttribute(score_kernel, cudaFuncAttributeMaxDynamicSharedMemorySize,
                         SMEM_TOTAL);

    prep_kernel<<<NCODES / 256, 256>>>(embed);
    transpose_split_kernel<<<dim3(NCODES / 32, K_DIM / 32), dim3(32, 32)>>>(embed);
    xq_kernel<<<(M_TOTAL * K_DIM / 4) / 256, 256>>>(x);
    score_kernel<<<dim3(M_TOTAL / MT, NSPLIT), THREADS, SMEM_TOTAL>>>();
    merge_kernel<<<M_TOTAL / 256, 256>>>();
    rescore_kernel<<<256, 256>>>(x);
    fixup_full_kernel<<<256, 256>>>(x);
    gather_kernel<<<M_TOTAL / 4, 256>>>(out);
}